// round 13
// baseline (speedup 1.0000x reference)
#include <cuda_runtime.h>
#include <cuda_fp16.h>
#include <cstdint>
#include <cstddef>

#define N_NODES 8192
#define IN_F    256
#define OUT_F   128
#define ALPHA   0.2f
#define NSPLIT  4
#define JCOLS   (N_NODES / NSPLIT)     // 2048 cols per CTA
#define NC      (JCOLS / 64)           // 32 chunks

// ---------------- device scratch (no allocations allowed) ----------------
__device__ __align__(16) __half  g_WhT[(size_t)OUT_F * N_NODES]; // [n][j] = Wh[j][n]
__device__ __align__(16) __half  g_WT[(size_t)OUT_F * IN_F];     // [n][k] = W[k][n]
__device__ float  g_src[N_NODES];
__device__ float  g_dst[N_NODES];
__device__ __align__(16) float4 g_rowpack[N_NODES];   // (E1', E2', 0, 0)
__device__ __align__(16) float2 g_colpack2[N_NODES];  // (F1', F2')  both <= 1
__device__ __align__(16) float  g_part[(size_t)NSPLIT * N_NODES * OUT_F];
__device__ float  g_rsum[NSPLIT * N_NODES];

__device__ __forceinline__ void cp16(uint32_t dst, const void* src) {
    asm volatile("cp.async.cg.shared.global [%0], [%1], 16;" :: "r"(dst), "l"(src) : "memory");
}
#define CPCOMMIT() asm volatile("cp.async.commit_group;" ::: "memory")
#define CPWAIT1()  asm volatile("cp.async.wait_group 1;" ::: "memory")
#define CPWAIT0()  asm volatile("cp.async.wait_group 0;" ::: "memory")

__device__ __forceinline__ void ldsm4(uint32_t& r0, uint32_t& r1, uint32_t& r2, uint32_t& r3,
                                      uint32_t addr) {
    asm volatile("ldmatrix.sync.aligned.m8n8.x4.shared.b16 {%0,%1,%2,%3}, [%4];"
                 : "=r"(r0), "=r"(r1), "=r"(r2), "=r"(r3) : "r"(addr));
}
__device__ __forceinline__ void mma_f32(float* c, const uint32_t* a, uint32_t b0, uint32_t b1) {
    asm volatile(
        "mma.sync.aligned.m16n8k16.row.col.f32.f16.f16.f32 "
        "{%0,%1,%2,%3}, {%4,%5,%6,%7}, {%8,%9}, {%0,%1,%2,%3};"
        : "+f"(c[0]), "+f"(c[1]), "+f"(c[2]), "+f"(c[3])
        : "r"(a[0]), "r"(a[1]), "r"(a[2]), "r"(a[3]), "r"(b0), "r"(b1));
}

// ============================================================================
// Kernel 0: transpose W -> g_WT fp16 [n][k].
// ============================================================================
__global__ __launch_bounds__(256) void k0_wt(const float* __restrict__ W) {
    int idx = blockIdx.x * 256 + threadIdx.x;     // 32768 total
    int k = idx >> 7, n = idx & 127;
    g_WT[(size_t)n * IN_F + k] = __float2half_rn(W[(size_t)k * OUT_F + n]);
}

// ============================================================================
// Kernel 1: Wh = h @ W via HMMA (fp16 in, fp32 acc). 256 CTAs x 32 rows.
// Emits WhT fp16 + src/dst vectors.
// ============================================================================
#define WT_OFF  0                       // 4 panels x 128 n x 128B = 65536
#define AH_OFF  65536                   // 4 panels x 32 rows x 128B = 16384
#define AV_OFF  81920                   // a_vec 256 floats = 1024
#define OT_OFF  82944                   // ot [128][48] halfs = 12288
#define SRD_OFF 95232                   // 64 floats
#define SMEM1   95488

__global__ __launch_bounds__(256, 2) void k1_wh(const float* __restrict__ h,
                                                const float* __restrict__ a_vec) {
    extern __shared__ char sm[];
    const uint32_t smu = (uint32_t)__cvta_generic_to_shared(sm);
    const int tid = threadIdx.x, lane = tid & 31, warp = tid >> 5;
    const int i0 = blockIdx.x * 32;

    // ---- stage WT via cp.async (swizzled panels: [kp][n][128B]) ----
#pragma unroll
    for (int c = 0; c < 16; ++c) {
        int idx = tid + c * 256;                   // 4096 chunks of 16B
        int n = idx >> 5, kc = idx & 31;           // kc: 8-half chunk along k
        int kp = kc >> 3, seg = kc & 7;
        cp16(smu + WT_OFF + kp * 16384 + n * 128 + ((seg ^ (n & 7)) << 4),
             &g_WT[(size_t)n * IN_F + kc * 8]);
    }
    CPCOMMIT();

    // ---- stage h tile (fp32 -> fp16, swizzled panels: [kp][row][128B]) ----
#pragma unroll
    for (int c = 0; c < 8; ++c) {
        int idx = tid + c * 256;                   // 2048 float4s
        int r = idx >> 6, q = idx & 63;            // q: float4 index along k
        float4 v = *(const float4*)&h[(size_t)(i0 + r) * IN_F + q * 4];
        __half2 h01 = __floats2half2_rn(v.x, v.y);
        __half2 h23 = __floats2half2_rn(v.z, v.w);
        uint2 u = make_uint2(*(uint32_t*)&h01, *(uint32_t*)&h23);
        int kp = q >> 4, seg = (q >> 1) & 7, off = (q & 1) * 8;
        *(uint2*)(sm + AH_OFF + kp * 4096 + r * 128 + ((seg ^ (r & 7)) << 4) + off) = u;
    }
    if (tid < 256) *(float*)(sm + AV_OFF + tid * 4) = a_vec[tid];
    if (tid < 64) *(float*)(sm + SRD_OFF + tid * 4) = 0.f;
    CPWAIT0();
    __syncthreads();

    // ---- HMMA: warp grid 2m x 4n, warp tile 16x32, K=256 (16 ks) ----
    const int wm = warp & 1, wn = warp >> 1;
    const int g = lane >> 2, t4 = lane & 3;
    const int lrA = (lane & 7) + ((lane >> 3) & 1) * 8;
    const int lkA = lane >> 4;
    const int lrB = (lane & 7) + ((lane >> 4) << 3);
    const int lkB = (lane >> 3) & 1;

    float acc[4][4];
#pragma unroll
    for (int nt = 0; nt < 4; ++nt)
#pragma unroll
        for (int e = 0; e < 4; ++e) acc[nt][e] = 0.f;

#pragma unroll
    for (int ks = 0; ks < 16; ++ks) {
        const int kp = ks >> 2, ksl = ks & 3;
        uint32_t a[4], b[2][4];
        {
            const int row = wm * 16 + lrA;
            const int seg = ksl * 2 + lkA;
            ldsm4(a[0], a[1], a[2], a[3],
                  smu + AH_OFF + kp * 4096 + row * 128 + ((seg ^ (row & 7)) << 4));
        }
#pragma unroll
        for (int np = 0; np < 2; ++np) {
            const int nr = wn * 32 + np * 16 + lrB;
            const int seg = ksl * 2 + lkB;
            ldsm4(b[np][0], b[np][1], b[np][2], b[np][3],
                  smu + WT_OFF + kp * 16384 + nr * 128 + ((seg ^ (nr & 7)) << 4));
        }
#pragma unroll
        for (int np = 0; np < 2; ++np) {
            mma_f32(acc[np * 2],     a, b[np][0], b[np][1]);
            mma_f32(acc[np * 2 + 1], a, b[np][2], b[np][3]);
        }
    }

    // ---- epilogue: src/dst partials + fp16 transpose staging ----
    const float* av = (const float*)(sm + AV_OFF);
    float* srd = (float*)(sm + SRD_OFF);
    float s0 = 0.f, s1 = 0.f, d0 = 0.f, d1 = 0.f;
#pragma unroll
    for (int nt = 0; nt < 4; ++nt) {
#pragma unroll
        for (int e = 0; e < 2; ++e) {
            const int cc = wn * 32 + nt * 8 + 2 * t4 + e;
            const float a1 = av[cc], a2 = av[128 + cc];
            s0 += acc[nt][e] * a1;     d0 += acc[nt][e] * a2;
            s1 += acc[nt][2 + e] * a1; d1 += acc[nt][2 + e] * a2;
        }
    }
    const int r0 = wm * 16 + g;
    atomicAdd(&srd[r0], s0);      atomicAdd(&srd[r0 + 8], s1);
    atomicAdd(&srd[32 + r0], d0); atomicAdd(&srd[32 + r0 + 8], d1);

    // ot[col][row], row stride 48 halfs (96B)
#pragma unroll
    for (int nt = 0; nt < 4; ++nt)
#pragma unroll
        for (int e = 0; e < 2; ++e) {
            const int cc = wn * 32 + nt * 8 + 2 * t4 + e;
            *(__half*)(sm + OT_OFF + cc * 96 + r0 * 2)       = __float2half_rn(acc[nt][e]);
            *(__half*)(sm + OT_OFF + cc * 96 + (r0 + 8) * 2) = __float2half_rn(acc[nt][2 + e]);
        }
    __syncthreads();

    // coalesced WhT write: 128 n x 4 (8-half segs)
#pragma unroll
    for (int c = 0; c < 2; ++c) {
        int idx = tid + c * 256;
        int n = idx >> 2, seg = idx & 3;
        *(uint4*)&g_WhT[(size_t)n * N_NODES + i0 + seg * 8] =
            *(uint4*)(sm + OT_OFF + n * 96 + seg * 16);
    }
    if (tid < 32) {
        g_src[i0 + tid] = srd[tid];
        g_dst[i0 + tid] = srd[32 + tid];
    }
}

// ============================================================================
// Kernel 2: global max(dst) + rescaled per-node exp tables (all factors <= 1).
//   rowpack = (E1', E2')  E1' = exp(s+Dmax-M), E2' = exp(a*(s+Dmax)-M)
//   colpack2 = (F1', F2') F1' = exp(d-Dmax),   F2' = exp(a*(d-Dmax))
//   w_ij = max(E1'F1', E2'F2') = exp(lrelu(s_i+d_j) - M_i)
// ============================================================================
__global__ __launch_bounds__(256) void k2_params() {
    __shared__ float red[256];
    const int tid = threadIdx.x;
    float m = -1e30f;
    for (int i = tid; i < N_NODES; i += 256) m = fmaxf(m, g_dst[i]);
    red[tid] = m;
    __syncthreads();
    for (int s = 128; s > 0; s >>= 1) {
        if (tid < s) red[tid] = fmaxf(red[tid], red[tid + s]);
        __syncthreads();
    }
    const float Dmax = red[0];
    for (int i = tid; i < N_NODES; i += 256) {
        float s = g_src[i], d = g_dst[i];
        float t = s + Dmax;
        float M = (t >= 0.f) ? t : ALPHA * t;
        g_rowpack[i] = make_float4(__expf(t - M), __expf(ALPHA * t - M), 0.f, 0.f);
        g_colpack2[i] = make_float2(__expf(d - Dmax), __expf(ALPHA * (d - Dmax)));
    }
}

// ============================================================================
// Kernel 3: fused masked-softmax weights + HMMA attention GEMM.
// 512 CTAs (128 row-tiles x 4 splits) x 256 thr, 64-row CTA, occupancy 2.
// adj+colpack: direct LDG with TWO-chunk register prefetch.
// B: triple-buffered cp.async. ONE barrier per chunk. max-form weights.
// ============================================================================
#define A3_OFF   0                       // 2 x 64 x 128B = 16384
#define B3_OFF   16384                   // 3 x 128 x 128B = 49152
#define RSP3_OFF 65536                   // 64 floats
#define SMEM3    65792

__device__ __forceinline__ void stage_B(uint32_t smu, int tid, int bbuf, size_t j0) {
#pragma unroll
    for (int c = 0; c < 4; ++c) {
        int idx = tid + c * 256;
        int n = idx >> 3, chn = idx & 7;
        cp16(smu + B3_OFF + bbuf * 16384 + n * 128 + ((chn ^ (n & 7)) << 4),
             &g_WhT[(size_t)n * N_NODES + j0 + chn * 8]);
    }
    CPCOMMIT();
}

__global__ __launch_bounds__(256, 2) void k3_attn(const int* __restrict__ adj) {
    extern __shared__ char sm[];
    const uint32_t smu = (uint32_t)__cvta_generic_to_shared(sm);
    const int tid = threadIdx.x, lane = tid & 31, warp = tid >> 5;
    const int split = blockIdx.x & 3;
    const int i0 = (blockIdx.x >> 2) * 64;
    const size_t jbase = (size_t)split * JCOLS;

    // wgen identity: thread owns 2 cols x 8 rows
    const int cp = tid & 31;                  // cols {2cp, 2cp+1}
    const int rg = tid >> 5;                  // rows rg*8 .. +7
    const int wseg = cp >> 2, woff = (cp & 3) * 4;
    // mma identity: 2m x 4n warps, warp tile 32 rows x 32 cols
    const int wm = warp & 1, wn = warp >> 1;
    const int g = lane >> 2, t4 = lane & 3;
    const int lrA = (lane & 7) + ((lane >> 3) & 1) * 8;
    const int lkA = lane >> 4;
    const int lrB = (lane & 7) + ((lane >> 4) << 3);
    const int lkB = (lane >> 3) & 1;
    const uint32_t bo = (g == 0) ? 0x3C003C00u : 0u;   // ones B frag (n==0)

    // rowpack factors for owned rows, in registers
    float rE1[8], rE2[8];
#pragma unroll
    for (int r = 0; r < 8; ++r) {
        float4 t = g_rowpack[i0 + rg * 8 + r];
        rE1[r] = t.x; rE2[r] = t.y;
    }
    const int* adj_base = adj + (size_t)(i0 + rg * 8) * N_NODES + jbase + 2 * cp;
    const float2* cp_base = g_colpack2 + jbase + 2 * cp;

    float acc[2][4][4];
    float accO[2][4];
#pragma unroll
    for (int mt = 0; mt < 2; ++mt) {
#pragma unroll
        for (int nt = 0; nt < 4; ++nt)
#pragma unroll
            for (int e = 0; e < 4; ++e) acc[mt][nt][e] = 0.f;
#pragma unroll
        for (int e = 0; e < 4; ++e) accO[mt][e] = 0.f;
    }

    uint2  ajA[8], ajB[8];
    float4 cA, cB;

    // load adj pair rows + colpack pair for chunk t into a register set
    auto ldgA = [&](int t) {
        const size_t joff = (size_t)t * 64;
#pragma unroll
        for (int r = 0; r < 8; ++r)
            ajA[r] = __ldg((const uint2*)(adj_base + (size_t)r * N_NODES + joff));
        cA = __ldg((const float4*)(cp_base + joff));
    };
    auto ldgB = [&](int t) {
        const size_t joff = (size_t)t * 64;
#pragma unroll
        for (int r = 0; r < 8; ++r)
            ajB[r] = __ldg((const uint2*)(adj_base + (size_t)r * N_NODES + joff));
        cB = __ldg((const float4*)(cp_base + joff));
    };
    // max-form weight gen from a register set -> swizzled A tile (fp16)
    auto wgenA = [&](int abuf_) {
        char* aw = sm + A3_OFF + abuf_ * 8192;
#pragma unroll
        for (int r = 0; r < 8; ++r) {
            const int row = rg * 8 + r;
            float w0 = fmaxf(rE1[r] * cA.x, rE2[r] * cA.y);
            float w1 = fmaxf(rE1[r] * cA.z, rE2[r] * cA.w);
            if (ajA[r].x == 0u) w0 = 0.f;
            if (ajA[r].y == 0u) w1 = 0.f;
            __half2 hw = __floats2half2_rn(w0, w1);
            *(uint32_t*)(aw + row * 128 + ((wseg ^ (row & 7)) << 4) + woff) =
                *(uint32_t*)&hw;
        }
    };
    auto wgenB = [&](int abuf_) {
        char* aw = sm + A3_OFF + abuf_ * 8192;
#pragma unroll
        for (int r = 0; r < 8; ++r) {
            const int row = rg * 8 + r;
            float w0 = fmaxf(rE1[r] * cB.x, rE2[r] * cB.y);
            float w1 = fmaxf(rE1[r] * cB.z, rE2[r] * cB.w);
            if (ajB[r].x == 0u) w0 = 0.f;
            if (ajB[r].y == 0u) w1 = 0.f;
            __half2 hw = __floats2half2_rn(w0, w1);
            *(uint32_t*)(aw + row * 128 + ((wseg ^ (row & 7)) << 4) + woff) =
                *(uint32_t*)&hw;
        }
    };

    // ---- prologue: chunk c lives in register set (c & 1) ----
    stage_B(smu, tid, 0, jbase);
    stage_B(smu, tid, 1, jbase + 64);
    ldgA(0);
    ldgB(1);
    wgenA(0);              // A[0]
    CPWAIT1();             // B(0) done, B(1) flying
    __syncthreads();

    // ---- main loop: ONE barrier per chunk; adj prefetched 2 chunks deep ----
    for (int t = 0; t < NC; ++t) {
        const int cur = t & 1;
        // prefetch chunk t+2 into the set that held chunk t (already consumed)
        if (t + 2 < NC) {
            if ((t & 1) == 0) ldgA(t + 2); else ldgB(t + 2);
        }
        if (t + 2 < NC) stage_B(smu, tid, (t + 2) % 3, jbase + (size_t)(t + 2) * 64);

        // mma(t): A[cur] x B[t%3]
        {
            const uint32_t aB = smu + A3_OFF + cur * 8192;
            const uint32_t bB = smu + B3_OFF + (t % 3) * 16384;
#pragma unroll
            for (int ks = 0; ks < 4; ++ks) {
                uint32_t a[2][4], b[2][4];
#pragma unroll
                for (int mt = 0; mt < 2; ++mt) {
                    const int row = wm * 32 + mt * 16 + lrA;
                    const int seg = 2 * ks + lkA;
                    ldsm4(a[mt][0], a[mt][1], a[mt][2], a[mt][3],
                          aB + row * 128 + ((seg ^ (row & 7)) << 4));
                }
#pragma unroll
                for (int np = 0; np < 2; ++np) {
                    const int nr = wn * 32 + np * 16 + lrB;
                    const int seg = 2 * ks + lkB;
                    ldsm4(b[np][0], b[np][1], b[np][2], b[np][3],
                          bB + nr * 128 + ((seg ^ (nr & 7)) << 4));
                }
#pragma unroll
                for (int mt = 0; mt < 2; ++mt) {
#pragma unroll
                    for (int np = 0; np < 2; ++np) {
                        mma_f32(acc[mt][np * 2],     a[mt], b[np][0], b[np][1]);
                        mma_f32(acc[mt][np * 2 + 1], a[mt], b[np][2], b[np][3]);
                    }
                    if (wn == 0) mma_f32(accO[mt], a[mt], bo, bo);
                }
            }
        }

        // wgen(t+1) into A[cur^1] from the set loaded 2 iterations ago
        if (t + 1 < NC) {
            if ((t + 1) & 1) wgenB(cur ^ 1); else wgenA(cur ^ 1);
        }

        if (t + 2 < NC) CPWAIT1();   // B(t+1) done, B(t+2) flying
        else CPWAIT0();
        __syncthreads();             // A[cur^1]+B(t+1) visible; mma(t) reads done
    }

    // ---- epilogue: partial outputs + row sums ----
    {
        float* pp = g_part + (size_t)split * N_NODES * OUT_F;
#pragma unroll
        for (int mt = 0; mt < 2; ++mt) {
            const int r0 = i0 + wm * 32 + mt * 16 + g;
#pragma unroll
            for (int nt = 0; nt < 4; ++nt) {
                const int cc = wn * 32 + nt * 8 + 2 * t4;
                *(float2*)&pp[(size_t)r0 * OUT_F + cc] =
                    make_float2(acc[mt][nt][0], acc[mt][nt][1]);
                *(float2*)&pp[(size_t)(r0 + 8) * OUT_F + cc] =
                    make_float2(acc[mt][nt][2], acc[mt][nt][3]);
            }
        }
    }
    float* rsp = (float*)(sm + RSP3_OFF);
    if (wn == 0 && t4 == 0) {
#pragma unroll
        for (int mt = 0; mt < 2; ++mt) {
            rsp[wm * 32 + mt * 16 + g]     = accO[mt][0];
            rsp[wm * 32 + mt * 16 + g + 8] = accO[mt][2];
        }
    }
    __syncthreads();
    if (tid < 64) g_rsum[split * N_NODES + i0 + tid] = rsp[tid];
}

// ============================================================================
// Kernel 4: combine 4 split partials, normalize, ELU, store. 1 float4/thread.
// ============================================================================
__device__ __forceinline__ float elu1(float x) {
    return x > 0.f ? x : (__expf(x) - 1.f);
}

__global__ __launch_bounds__(256) void k4_fin(float* __restrict__ out) {
    int gi = blockIdx.x * 256 + threadIdx.x;      // 262144 threads
    int row = gi >> 5;
    int cof = (gi & 31) * 4;
    const float* pb = g_part + (size_t)row * OUT_F + cof;
    float4 a = *(const float4*)pb;
    float4 b = *(const float4*)(pb + (size_t)N_NODES * OUT_F);
    float4 c = *(const float4*)(pb + 2 * (size_t)N_NODES * OUT_F);
    float4 d = *(const float4*)(pb + 3 * (size_t)N_NODES * OUT_F);
    float s = g_rsum[row] + g_rsum[N_NODES + row]
            + g_rsum[2 * N_NODES + row] + g_rsum[3 * N_NODES + row];
    float rinv = 1.f / s;
    float4 o;
    o.x = elu1((a.x + b.x + c.x + d.x) * rinv);
    o.y = elu1((a.y + b.y + c.y + d.y) * rinv);
    o.z = elu1((a.z + b.z + c.z + d.z) * rinv);
    o.w = elu1((a.w + b.w + c.w + d.w) * rinv);
    *(float4*)(out + (size_t)row * OUT_F + cof) = o;
}

// ============================================================================
extern "C" void kernel_launch(void* const* d_in, const int* in_sizes, int n_in,
                              void* d_out, int out_size) {
    const float* h   = (const float*)d_in[0];
    const int*   adj = (const int*)d_in[1];
    const float* W   = (const float*)d_in[2];
    const float* a   = (const float*)d_in[3];
    float* out = (float*)d_out;
    (void)in_sizes; (void)n_in; (void)out_size;

    cudaFuncSetAttribute(k1_wh, cudaFuncAttributeMaxDynamicSharedMemorySize, SMEM1);
    cudaFuncSetAttribute(k3_attn, cudaFuncAttributeMaxDynamicSharedMemorySize, SMEM3);

    k0_wt<<<(IN_F * OUT_F) / 256, 256>>>(W);
    k1_wh<<<N_NODES / 32, 256, SMEM1>>>(h, a);
    k2_params<<<1, 256>>>();
    k3_attn<<<(N_NODES / 64) * NSPLIT, 256, SMEM3>>>(adj);
    k4_fin<<<(N_NODES * OUT_F / 4) / 256, 256>>>(out);
}

// round 14
// speedup vs baseline: 1.5250x; 1.5250x over previous
#include <cuda_runtime.h>
#include <cuda_fp16.h>
#include <cstdint>
#include <cstddef>

#define N_NODES 8192
#define IN_F    256
#define OUT_F   128
#define ALPHA   0.2f
#define NSPLIT  4
#define JCOLS   (N_NODES / NSPLIT)     // 2048 cols per CTA
#define NC      (JCOLS / 64)           // 32 chunks

// ---------------- device scratch (no allocations allowed) ----------------
__device__ __align__(16) __half  g_WhT[(size_t)OUT_F * N_NODES]; // [n][j] = Wh[j][n]
__device__ __align__(16) __half  g_WT[(size_t)OUT_F * IN_F];     // [n][k] = W[k][n]
__device__ float  g_src[N_NODES];
__device__ float  g_dst[N_NODES];
__device__ __align__(16) float4 g_rowpack[N_NODES];   // (E1', E2', 0, 0)
__device__ __align__(16) float2 g_colpack2[N_NODES];  // (F1', F2')  both <= 1
__device__ __align__(16) float  g_part[(size_t)NSPLIT * N_NODES * OUT_F];
__device__ float  g_rsum[NSPLIT * N_NODES];

__device__ __forceinline__ void cp16(uint32_t dst, const void* src) {
    asm volatile("cp.async.cg.shared.global [%0], [%1], 16;" :: "r"(dst), "l"(src) : "memory");
}
#define CPCOMMIT() asm volatile("cp.async.commit_group;" ::: "memory")
#define CPWAIT1()  asm volatile("cp.async.wait_group 1;" ::: "memory")
#define CPWAIT0()  asm volatile("cp.async.wait_group 0;" ::: "memory")

__device__ __forceinline__ void ldsm4(uint32_t& r0, uint32_t& r1, uint32_t& r2, uint32_t& r3,
                                      uint32_t addr) {
    asm volatile("ldmatrix.sync.aligned.m8n8.x4.shared.b16 {%0,%1,%2,%3}, [%4];"
                 : "=r"(r0), "=r"(r1), "=r"(r2), "=r"(r3) : "r"(addr));
}
__device__ __forceinline__ void mma_f32(float* c, const uint32_t* a, uint32_t b0, uint32_t b1) {
    asm volatile(
        "mma.sync.aligned.m16n8k16.row.col.f32.f16.f16.f32 "
        "{%0,%1,%2,%3}, {%4,%5,%6,%7}, {%8,%9}, {%0,%1,%2,%3};"
        : "+f"(c[0]), "+f"(c[1]), "+f"(c[2]), "+f"(c[3])
        : "r"(a[0]), "r"(a[1]), "r"(a[2]), "r"(a[3]), "r"(b0), "r"(b1));
}

// ============================================================================
// Kernel 0: transpose W -> g_WT fp16 [n][k].
// ============================================================================
__global__ __launch_bounds__(256) void k0_wt(const float* __restrict__ W) {
    int idx = blockIdx.x * 256 + threadIdx.x;     // 32768 total
    int k = idx >> 7, n = idx & 127;
    g_WT[(size_t)n * IN_F + k] = __float2half_rn(W[(size_t)k * OUT_F + n]);
}

// ============================================================================
// Kernel 1: Wh = h @ W via HMMA (fp16 in, fp32 acc). 256 CTAs x 32 rows.
// Emits WhT fp16 + src/dst vectors.
// ============================================================================
#define WT_OFF  0                       // 4 panels x 128 n x 128B = 65536
#define AH_OFF  65536                   // 4 panels x 32 rows x 128B = 16384
#define AV_OFF  81920                   // a_vec 256 floats = 1024
#define OT_OFF  82944                   // ot [128][48] halfs = 12288
#define SRD_OFF 95232                   // 64 floats
#define SMEM1   95488

__global__ __launch_bounds__(256, 2) void k1_wh(const float* __restrict__ h,
                                                const float* __restrict__ a_vec) {
    extern __shared__ char sm[];
    const uint32_t smu = (uint32_t)__cvta_generic_to_shared(sm);
    const int tid = threadIdx.x, lane = tid & 31, warp = tid >> 5;
    const int i0 = blockIdx.x * 32;

    // ---- stage WT via cp.async (swizzled panels: [kp][n][128B]) ----
#pragma unroll
    for (int c = 0; c < 16; ++c) {
        int idx = tid + c * 256;                   // 4096 chunks of 16B
        int n = idx >> 5, kc = idx & 31;           // kc: 8-half chunk along k
        int kp = kc >> 3, seg = kc & 7;
        cp16(smu + WT_OFF + kp * 16384 + n * 128 + ((seg ^ (n & 7)) << 4),
             &g_WT[(size_t)n * IN_F + kc * 8]);
    }
    CPCOMMIT();

    // ---- stage h tile (fp32 -> fp16, swizzled panels: [kp][row][128B]) ----
#pragma unroll
    for (int c = 0; c < 8; ++c) {
        int idx = tid + c * 256;                   // 2048 float4s
        int r = idx >> 6, q = idx & 63;            // q: float4 index along k
        float4 v = *(const float4*)&h[(size_t)(i0 + r) * IN_F + q * 4];
        __half2 h01 = __floats2half2_rn(v.x, v.y);
        __half2 h23 = __floats2half2_rn(v.z, v.w);
        uint2 u = make_uint2(*(uint32_t*)&h01, *(uint32_t*)&h23);
        int kp = q >> 4, seg = (q >> 1) & 7, off = (q & 1) * 8;
        *(uint2*)(sm + AH_OFF + kp * 4096 + r * 128 + ((seg ^ (r & 7)) << 4) + off) = u;
    }
    if (tid < 256) *(float*)(sm + AV_OFF + tid * 4) = a_vec[tid];
    if (tid < 64) *(float*)(sm + SRD_OFF + tid * 4) = 0.f;
    CPWAIT0();
    __syncthreads();

    // ---- HMMA: warp grid 2m x 4n, warp tile 16x32, K=256 (16 ks) ----
    const int wm = warp & 1, wn = warp >> 1;
    const int g = lane >> 2, t4 = lane & 3;
    const int lrA = (lane & 7) + ((lane >> 3) & 1) * 8;
    const int lkA = lane >> 4;
    const int lrB = (lane & 7) + ((lane >> 4) << 3);
    const int lkB = (lane >> 3) & 1;

    float acc[4][4];
#pragma unroll
    for (int nt = 0; nt < 4; ++nt)
#pragma unroll
        for (int e = 0; e < 4; ++e) acc[nt][e] = 0.f;

#pragma unroll
    for (int ks = 0; ks < 16; ++ks) {
        const int kp = ks >> 2, ksl = ks & 3;
        uint32_t a[4], b[2][4];
        {
            const int row = wm * 16 + lrA;
            const int seg = ksl * 2 + lkA;
            ldsm4(a[0], a[1], a[2], a[3],
                  smu + AH_OFF + kp * 4096 + row * 128 + ((seg ^ (row & 7)) << 4));
        }
#pragma unroll
        for (int np = 0; np < 2; ++np) {
            const int nr = wn * 32 + np * 16 + lrB;
            const int seg = ksl * 2 + lkB;
            ldsm4(b[np][0], b[np][1], b[np][2], b[np][3],
                  smu + WT_OFF + kp * 16384 + nr * 128 + ((seg ^ (nr & 7)) << 4));
        }
#pragma unroll
        for (int np = 0; np < 2; ++np) {
            mma_f32(acc[np * 2],     a, b[np][0], b[np][1]);
            mma_f32(acc[np * 2 + 1], a, b[np][2], b[np][3]);
        }
    }

    // ---- epilogue: src/dst partials + fp16 transpose staging ----
    const float* av = (const float*)(sm + AV_OFF);
    float* srd = (float*)(sm + SRD_OFF);
    float s0 = 0.f, s1 = 0.f, d0 = 0.f, d1 = 0.f;
#pragma unroll
    for (int nt = 0; nt < 4; ++nt) {
#pragma unroll
        for (int e = 0; e < 2; ++e) {
            const int cc = wn * 32 + nt * 8 + 2 * t4 + e;
            const float a1 = av[cc], a2 = av[128 + cc];
            s0 += acc[nt][e] * a1;     d0 += acc[nt][e] * a2;
            s1 += acc[nt][2 + e] * a1; d1 += acc[nt][2 + e] * a2;
        }
    }
    const int r0 = wm * 16 + g;
    atomicAdd(&srd[r0], s0);      atomicAdd(&srd[r0 + 8], s1);
    atomicAdd(&srd[32 + r0], d0); atomicAdd(&srd[32 + r0 + 8], d1);

    // ot[col][row], row stride 48 halfs (96B)
#pragma unroll
    for (int nt = 0; nt < 4; ++nt)
#pragma unroll
        for (int e = 0; e < 2; ++e) {
            const int cc = wn * 32 + nt * 8 + 2 * t4 + e;
            *(__half*)(sm + OT_OFF + cc * 96 + r0 * 2)       = __float2half_rn(acc[nt][e]);
            *(__half*)(sm + OT_OFF + cc * 96 + (r0 + 8) * 2) = __float2half_rn(acc[nt][2 + e]);
        }
    __syncthreads();

    // coalesced WhT write: 128 n x 4 (8-half segs)
#pragma unroll
    for (int c = 0; c < 2; ++c) {
        int idx = tid + c * 256;
        int n = idx >> 2, seg = idx & 3;
        *(uint4*)&g_WhT[(size_t)n * N_NODES + i0 + seg * 8] =
            *(uint4*)(sm + OT_OFF + n * 96 + seg * 16);
    }
    if (tid < 32) {
        g_src[i0 + tid] = srd[tid];
        g_dst[i0 + tid] = srd[32 + tid];
    }
}

// ============================================================================
// Kernel 2: global max(dst) + rescaled per-node exp tables (all factors <= 1).
//   rowpack  = (E1', E2')  E1' = exp(s+Dmax-M), E2' = exp(a*(s+Dmax)-M)
//   colpack2 = (F1', F2')  F1' = exp(d-Dmax),   F2' = exp(a*(d-Dmax))
//   w_ij = max(E1'F1', E2'F2') = exp(lrelu(s_i+d_j) - M_i)
// ============================================================================
__global__ __launch_bounds__(256) void k2_params() {
    __shared__ float red[256];
    const int tid = threadIdx.x;
    float m = -1e30f;
    for (int i = tid; i < N_NODES; i += 256) m = fmaxf(m, g_dst[i]);
    red[tid] = m;
    __syncthreads();
    for (int s = 128; s > 0; s >>= 1) {
        if (tid < s) red[tid] = fmaxf(red[tid], red[tid + s]);
        __syncthreads();
    }
    const float Dmax = red[0];
    for (int i = tid; i < N_NODES; i += 256) {
        float s = g_src[i], d = g_dst[i];
        float t = s + Dmax;
        float M = (t >= 0.f) ? t : ALPHA * t;
        g_rowpack[i] = make_float4(__expf(t - M), __expf(ALPHA * t - M), 0.f, 0.f);
        g_colpack2[i] = make_float2(__expf(d - Dmax), __expf(ALPHA * (d - Dmax)));
    }
}

// ============================================================================
// Kernel 3: fused masked-softmax weights + HMMA attention GEMM.
// R9-proven pipeline: 512 CTAs x 256 thr, 64-row CTA, occupancy 2,
// adj+colpack 3-deep cp.async staging, B double-buffered.
// New: max-form weights, colpack2, rsum via wgen FADDs, 2m x 4n warp tiles.
// ============================================================================
#define A3_OFF   0                       // 2 x 64 x 128B = 16384
#define B3_OFF   16384                   // 2 x 128 x 128B = 32768
#define ADJ3_OFF 49152                   // 3 x 64 x 256B = 49152
#define CP3_OFF  98304                   // 3 x 64 x 8B = 1536
#define RSP3_OFF 99840                   // 64 floats
#define SMEM3    100096

// stage B tile (chunk j0) into buffer bbuf — its own commit group
__device__ __forceinline__ void stage_B(uint32_t smu, int tid, int bbuf, size_t j0) {
#pragma unroll
    for (int c = 0; c < 4; ++c) {
        int idx = tid + c * 256;
        int n = idx >> 3, chn = idx & 7;
        cp16(smu + B3_OFF + bbuf * 16384 + n * 128 + ((chn ^ (n & 7)) << 4),
             &g_WhT[(size_t)n * N_NODES + j0 + chn * 8]);
    }
    CPCOMMIT();
}
// stage adj + colpack2 (chunk j0) into buffer abuf — its own commit group
__device__ __forceinline__ void stage_ADJ(uint32_t smu, int tid, int abuf,
                                          const int* adj, int i0, size_t j0) {
#pragma unroll
    for (int c = 0; c < 4; ++c) {
        int idx = tid + c * 256;
        int row = idx >> 4, seg = idx & 15;
        cp16(smu + ADJ3_OFF + abuf * 16384 + row * 256 + seg * 16,
             adj + (size_t)(i0 + row) * N_NODES + j0 + seg * 4);
    }
    if (tid < 32)
        cp16(smu + CP3_OFF + abuf * 512 + tid * 16, &g_colpack2[j0 + tid * 2]);
    CPCOMMIT();
}

__global__ __launch_bounds__(256, 2) void k3_attn(const int* __restrict__ adj) {
    extern __shared__ char sm[];
    const uint32_t smu = (uint32_t)__cvta_generic_to_shared(sm);
    const int tid = threadIdx.x, lane = tid & 31, warp = tid >> 5;
    const int split = blockIdx.x & 3;
    const int i0 = (blockIdx.x >> 2) * 64;
    const size_t jbase = (size_t)split * JCOLS;

    // wgen identity: warp rg owns rows rg*8..+7; lane cp owns cols {2cp, 2cp+1}
    const int cp = lane;
    const int rg = warp;
    const int wseg = cp >> 2, woff = (cp & 3) * 4;
    // mma identity: 2m x 4n warps, warp tile 32 rows x 32 cols
    const int wm = warp & 1, wn = warp >> 1;
    const int g = lane >> 2, t4 = lane & 3;
    const int lrA = (lane & 7) + ((lane >> 3) & 1) * 8;
    const int lkA = lane >> 4;
    const int lrB = (lane & 7) + ((lane >> 4) << 3);
    const int lkB = (lane >> 3) & 1;

    // rowpack factors for owned rows, in registers
    float rE1[8], rE2[8];
#pragma unroll
    for (int r = 0; r < 8; ++r) {
        float4 t = g_rowpack[i0 + rg * 8 + r];
        rE1[r] = t.x; rE2[r] = t.y;
    }

    float acc[2][4][4];
    float rs[8];                          // per-owned-row weight sums
#pragma unroll
    for (int mt = 0; mt < 2; ++mt)
#pragma unroll
        for (int nt = 0; nt < 4; ++nt)
#pragma unroll
            for (int e = 0; e < 4; ++e) acc[mt][nt][e] = 0.f;
#pragma unroll
    for (int r = 0; r < 8; ++r) rs[r] = 0.f;

    // wgen: adj[abuf] + colpack2[abuf] (smem) -> swizzled A tile + rsum FADDs
    auto wgen = [&](int abuf_, int cur_) {
        const float4 cc = *(const float4*)(sm + CP3_OFF + abuf_ * 512 + cp * 16);
        const char* ab = sm + ADJ3_OFF + abuf_ * 16384 + cp * 8;
        char* aw = sm + A3_OFF + cur_ * 8192;
#pragma unroll
        for (int r = 0; r < 8; ++r) {
            const int row = rg * 8 + r;
            uint2 av = *(const uint2*)(ab + row * 256);
            float w0 = fmaxf(rE1[r] * cc.x, rE2[r] * cc.y);
            float w1 = fmaxf(rE1[r] * cc.z, rE2[r] * cc.w);
            if (av.x == 0u) w0 = 0.f;
            if (av.y == 0u) w1 = 0.f;
            rs[r] += w0 + w1;
            __half2 hw = __floats2half2_rn(w0, w1);
            *(uint32_t*)(aw + row * 128 + ((wseg ^ (row & 7)) << 4) + woff) =
                *(uint32_t*)&hw;
        }
    };

    // ---- prologue: adj(0), B(0), adj(1) in flight; drain first two ----
    stage_ADJ(smu, tid, 0, adj, i0, jbase);
    stage_B(smu, tid, 0, jbase);
    stage_ADJ(smu, tid, 1, adj, i0, jbase + 64);
    CPWAIT1();            // adj(0), B(0) done; adj(1) flying
    __syncthreads();

    // ---- main loop ----
    int abuf = 0;         // adj buffer of chunk t (mod 3)
    for (int t = 0; t < NC; ++t) {
        const int cur = t & 1, nxt = cur ^ 1;

        wgen(abuf, cur);

        if (t + 1 < NC) stage_B(smu, tid, nxt, jbase + (size_t)(t + 1) * 64);
        if (t + 2 < NC) {
            int a2 = abuf + 2; if (a2 >= 3) a2 -= 3;
            stage_ADJ(smu, tid, a2, adj, i0, jbase + (size_t)(t + 2) * 64);
        }
        __syncthreads();   // A[cur] visible for mma

        // mma(t): A[cur] x B[cur]
        {
            const uint32_t aB = smu + A3_OFF + cur * 8192;
            const uint32_t bB = smu + B3_OFF + cur * 16384;
#pragma unroll
            for (int ks = 0; ks < 4; ++ks) {
                uint32_t a[2][4], b[2][4];
#pragma unroll
                for (int mt = 0; mt < 2; ++mt) {
                    const int row = wm * 32 + mt * 16 + lrA;
                    const int seg = 2 * ks + lkA;
                    ldsm4(a[mt][0], a[mt][1], a[mt][2], a[mt][3],
                          aB + row * 128 + ((seg ^ (row & 7)) << 4));
                }
#pragma unroll
                for (int np = 0; np < 2; ++np) {
                    const int nr = wn * 32 + np * 16 + lrB;
                    const int seg = 2 * ks + lkB;
                    ldsm4(b[np][0], b[np][1], b[np][2], b[np][3],
                          bB + nr * 128 + ((seg ^ (nr & 7)) << 4));
                }
#pragma unroll
                for (int mt = 0; mt < 2; ++mt)
#pragma unroll
                    for (int np = 0; np < 2; ++np) {
                        mma_f32(acc[mt][np * 2],     a[mt], b[np][0], b[np][1]);
                        mma_f32(acc[mt][np * 2 + 1], a[mt], b[np][2], b[np][3]);
                    }
            }
        }

        if (t + 2 < NC) CPWAIT1();   // adj(t+1), B(t+1) done; adj(t+2) flying
        else CPWAIT0();
        __syncthreads();

        if (++abuf >= 3) abuf -= 3;
    }

    // ---- epilogue: partial outputs + row sums ----
    {
        float* pp = g_part + (size_t)split * N_NODES * OUT_F;
#pragma unroll
        for (int mt = 0; mt < 2; ++mt) {
            const int r0 = i0 + wm * 32 + mt * 16 + g;
#pragma unroll
            for (int nt = 0; nt < 4; ++nt) {
                const int cc = wn * 32 + nt * 8 + 2 * t4;
                *(float2*)&pp[(size_t)r0 * OUT_F + cc] =
                    make_float2(acc[mt][nt][0], acc[mt][nt][1]);
                *(float2*)&pp[(size_t)(r0 + 8) * OUT_F + cc] =
                    make_float2(acc[mt][nt][2], acc[mt][nt][3]);
            }
        }
    }
    // row sums: warp-reduce rs[r] across 32 col-owner lanes
    float* rsp = (float*)(sm + RSP3_OFF);
#pragma unroll
    for (int r = 0; r < 8; ++r) {
        float v = rs[r];
#pragma unroll
        for (int off = 16; off > 0; off >>= 1)
            v += __shfl_xor_sync(0xffffffffu, v, off);
        if (lane == 0) rsp[rg * 8 + r] = v;
    }
    __syncthreads();
    if (tid < 64) g_rsum[split * N_NODES + i0 + tid] = rsp[tid];
}

// ============================================================================
// Kernel 4: combine 4 split partials, normalize, ELU, store. 1 float4/thread.
// ============================================================================
__device__ __forceinline__ float elu1(float x) {
    return x > 0.f ? x : (__expf(x) - 1.f);
}

__global__ __launch_bounds__(256) void k4_fin(float* __restrict__ out) {
    int gi = blockIdx.x * 256 + threadIdx.x;      // 262144 threads
    int row = gi >> 5;
    int cof = (gi & 31) * 4;
    const float* pb = g_part + (size_t)row * OUT_F + cof;
    float4 a = *(const float4*)pb;
    float4 b = *(const float4*)(pb + (size_t)N_NODES * OUT_F);
    float4 c = *(const float4*)(pb + 2 * (size_t)N_NODES * OUT_F);
    float4 d = *(const float4*)(pb + 3 * (size_t)N_NODES * OUT_F);
    float s = g_rsum[row] + g_rsum[N_NODES + row]
            + g_rsum[2 * N_NODES + row] + g_rsum[3 * N_NODES + row];
    float rinv = 1.f / s;
    float4 o;
    o.x = elu1((a.x + b.x + c.x + d.x) * rinv);
    o.y = elu1((a.y + b.y + c.y + d.y) * rinv);
    o.z = elu1((a.z + b.z + c.z + d.z) * rinv);
    o.w = elu1((a.w + b.w + c.w + d.w) * rinv);
    *(float4*)(out + (size_t)row * OUT_F + cof) = o;
}

// ============================================================================
extern "C" void kernel_launch(void* const* d_in, const int* in_sizes, int n_in,
                              void* d_out, int out_size) {
    const float* h   = (const float*)d_in[0];
    const int*   adj = (const int*)d_in[1];
    const float* W   = (const float*)d_in[2];
    const float* a   = (const float*)d_in[3];
    float* out = (float*)d_out;
    (void)in_sizes; (void)n_in; (void)out_size;

    cudaFuncSetAttribute(k1_wh, cudaFuncAttributeMaxDynamicSharedMemorySize, SMEM1);
    cudaFuncSetAttribute(k3_attn, cudaFuncAttributeMaxDynamicSharedMemorySize, SMEM3);

    k0_wt<<<(IN_F * OUT_F) / 256, 256>>>(W);
    k1_wh<<<N_NODES / 32, 256, SMEM1>>>(h, a);
    k2_params<<<1, 256>>>();
    k3_attn<<<(N_NODES / 64) * NSPLIT, 256, SMEM3>>>(adj);
    k4_fin<<<(N_NODES * OUT_F / 4) / 256, 256>>>(out);
}

// round 17
// speedup vs baseline: 1.5496x; 1.0161x over previous
#include <cuda_runtime.h>
#include <cuda_fp16.h>
#include <cstdint>
#include <cstddef>

#define N_NODES 8192
#define IN_F    256
#define OUT_F   128
#define ALPHA   0.2f
#define NSPLIT  4
#define JCOLS   (N_NODES / NSPLIT)     // 2048 cols per CTA
#define NC      (JCOLS / 64)           // 32 chunks

// ---------------- device scratch (no allocations allowed) ----------------
__device__ __align__(16) __half  g_WhT[(size_t)OUT_F * N_NODES]; // [n][j] = Wh[j][n]
__device__ __align__(16) __half  g_WT[(size_t)OUT_F * IN_F];     // [n][k] = W[k][n]
__device__ float  g_src[N_NODES];
__device__ float  g_dst[N_NODES];
__device__ __align__(16) float4 g_rowpack[N_NODES];   // (E1', E2', 0, 0)
__device__ __align__(16) float2 g_colpack2[N_NODES];  // (F1', F2')  both <= 1
__device__ __align__(16) float  g_part[(size_t)NSPLIT * N_NODES * OUT_F];
__device__ float  g_rsum[NSPLIT * N_NODES];

__device__ __forceinline__ void cp16(uint32_t dst, const void* src) {
    asm volatile("cp.async.cg.shared.global [%0], [%1], 16;" :: "r"(dst), "l"(src) : "memory");
}
#define CPCOMMIT() asm volatile("cp.async.commit_group;" ::: "memory")
#define CPWAIT2()  asm volatile("cp.async.wait_group 2;" ::: "memory")
#define CPWAIT1()  asm volatile("cp.async.wait_group 1;" ::: "memory")
#define CPWAIT0()  asm volatile("cp.async.wait_group 0;" ::: "memory")

__device__ __forceinline__ void ldsm4(uint32_t& r0, uint32_t& r1, uint32_t& r2, uint32_t& r3,
                                      uint32_t addr) {
    asm volatile("ldmatrix.sync.aligned.m8n8.x4.shared.b16 {%0,%1,%2,%3}, [%4];"
                 : "=r"(r0), "=r"(r1), "=r"(r2), "=r"(r3) : "r"(addr));
}
__device__ __forceinline__ void mma_f32(float* c, const uint32_t* a, uint32_t b0, uint32_t b1) {
    asm volatile(
        "mma.sync.aligned.m16n8k16.row.col.f32.f16.f16.f32 "
        "{%0,%1,%2,%3}, {%4,%5,%6,%7}, {%8,%9}, {%0,%1,%2,%3};"
        : "+f"(c[0]), "+f"(c[1]), "+f"(c[2]), "+f"(c[3])
        : "r"(a[0]), "r"(a[1]), "r"(a[2]), "r"(a[3]), "r"(b0), "r"(b1));
}

// ============================================================================
// Kernel 0: transpose W -> g_WT fp16 [n][k].
// ============================================================================
__global__ __launch_bounds__(256) void k0_wt(const float* __restrict__ W) {
    int idx = blockIdx.x * 256 + threadIdx.x;     // 32768 total
    int k = idx >> 7, n = idx & 127;
    g_WT[(size_t)n * IN_F + k] = __float2half_rn(W[(size_t)k * OUT_F + n]);
}

// ============================================================================
// Kernel 1: Wh = h @ W via HMMA (fp16 in, fp32 acc). 256 CTAs x 32 rows.
// Emits WhT fp16 + src/dst vectors.
// ============================================================================
#define WT_OFF  0                       // 4 panels x 128 n x 128B = 65536
#define AH_OFF  65536                   // 4 panels x 32 rows x 128B = 16384
#define AV_OFF  81920                   // a_vec 256 floats = 1024
#define OT_OFF  82944                   // ot [128][48] halfs = 12288
#define SRD_OFF 95232                   // 64 floats
#define SMEM1   95488

__global__ __launch_bounds__(256, 2) void k1_wh(const float* __restrict__ h,
                                                const float* __restrict__ a_vec) {
    extern __shared__ char sm[];
    const uint32_t smu = (uint32_t)__cvta_generic_to_shared(sm);
    const int tid = threadIdx.x, lane = tid & 31, warp = tid >> 5;
    const int i0 = blockIdx.x * 32;

    // ---- stage WT via cp.async (swizzled panels: [kp][n][128B]) ----
#pragma unroll
    for (int c = 0; c < 16; ++c) {
        int idx = tid + c * 256;                   // 4096 chunks of 16B
        int n = idx >> 5, kc = idx & 31;           // kc: 8-half chunk along k
        int kp = kc >> 3, seg = kc & 7;
        cp16(smu + WT_OFF + kp * 16384 + n * 128 + ((seg ^ (n & 7)) << 4),
             &g_WT[(size_t)n * IN_F + kc * 8]);
    }
    CPCOMMIT();

    // ---- stage h tile (fp32 -> fp16, swizzled panels: [kp][row][128B]) ----
#pragma unroll
    for (int c = 0; c < 8; ++c) {
        int idx = tid + c * 256;                   // 2048 float4s
        int r = idx >> 6, q = idx & 63;            // q: float4 index along k
        float4 v = *(const float4*)&h[(size_t)(i0 + r) * IN_F + q * 4];
        __half2 h01 = __floats2half2_rn(v.x, v.y);
        __half2 h23 = __floats2half2_rn(v.z, v.w);
        uint2 u = make_uint2(*(uint32_t*)&h01, *(uint32_t*)&h23);
        int kp = q >> 4, seg = (q >> 1) & 7, off = (q & 1) * 8;
        *(uint2*)(sm + AH_OFF + kp * 4096 + r * 128 + ((seg ^ (r & 7)) << 4) + off) = u;
    }
    if (tid < 256) *(float*)(sm + AV_OFF + tid * 4) = a_vec[tid];
    if (tid < 64) *(float*)(sm + SRD_OFF + tid * 4) = 0.f;
    CPWAIT0();
    __syncthreads();

    // ---- HMMA: warp grid 2m x 4n, warp tile 16x32, K=256 (16 ks) ----
    const int wm = warp & 1, wn = warp >> 1;
    const int g = lane >> 2, t4 = lane & 3;
    const int lrA = (lane & 7) + ((lane >> 3) & 1) * 8;
    const int lkA = lane >> 4;
    const int lrB = (lane & 7) + ((lane >> 4) << 3);
    const int lkB = (lane >> 3) & 1;

    float acc[4][4];
#pragma unroll
    for (int nt = 0; nt < 4; ++nt)
#pragma unroll
        for (int e = 0; e < 4; ++e) acc[nt][e] = 0.f;

#pragma unroll
    for (int ks = 0; ks < 16; ++ks) {
        const int kp = ks >> 2, ksl = ks & 3;
        uint32_t a[4], b[2][4];
        {
            const int row = wm * 16 + lrA;
            const int seg = ksl * 2 + lkA;
            ldsm4(a[0], a[1], a[2], a[3],
                  smu + AH_OFF + kp * 4096 + row * 128 + ((seg ^ (row & 7)) << 4));
        }
#pragma unroll
        for (int np = 0; np < 2; ++np) {
            const int nr = wn * 32 + np * 16 + lrB;
            const int seg = ksl * 2 + lkB;
            ldsm4(b[np][0], b[np][1], b[np][2], b[np][3],
                  smu + WT_OFF + kp * 16384 + nr * 128 + ((seg ^ (nr & 7)) << 4));
        }
#pragma unroll
        for (int np = 0; np < 2; ++np) {
            mma_f32(acc[np * 2],     a, b[np][0], b[np][1]);
            mma_f32(acc[np * 2 + 1], a, b[np][2], b[np][3]);
        }
    }

    // ---- epilogue: src/dst partials + fp16 transpose staging ----
    const float* av = (const float*)(sm + AV_OFF);
    float* srd = (float*)(sm + SRD_OFF);
    float s0 = 0.f, s1 = 0.f, d0 = 0.f, d1 = 0.f;
#pragma unroll
    for (int nt = 0; nt < 4; ++nt) {
#pragma unroll
        for (int e = 0; e < 2; ++e) {
            const int cc = wn * 32 + nt * 8 + 2 * t4 + e;
            const float a1 = av[cc], a2 = av[128 + cc];
            s0 += acc[nt][e] * a1;     d0 += acc[nt][e] * a2;
            s1 += acc[nt][2 + e] * a1; d1 += acc[nt][2 + e] * a2;
        }
    }
    const int r0 = wm * 16 + g;
    atomicAdd(&srd[r0], s0);      atomicAdd(&srd[r0 + 8], s1);
    atomicAdd(&srd[32 + r0], d0); atomicAdd(&srd[32 + r0 + 8], d1);

    // ot[col][row], row stride 48 halfs (96B)
#pragma unroll
    for (int nt = 0; nt < 4; ++nt)
#pragma unroll
        for (int e = 0; e < 2; ++e) {
            const int cc = wn * 32 + nt * 8 + 2 * t4 + e;
            *(__half*)(sm + OT_OFF + cc * 96 + r0 * 2)       = __float2half_rn(acc[nt][e]);
            *(__half*)(sm + OT_OFF + cc * 96 + (r0 + 8) * 2) = __float2half_rn(acc[nt][2 + e]);
        }
    __syncthreads();

    // coalesced WhT write: 128 n x 4 (8-half segs)
#pragma unroll
    for (int c = 0; c < 2; ++c) {
        int idx = tid + c * 256;
        int n = idx >> 2, seg = idx & 3;
        *(uint4*)&g_WhT[(size_t)n * N_NODES + i0 + seg * 8] =
            *(uint4*)(sm + OT_OFF + n * 96 + seg * 16);
    }
    if (tid < 32) {
        g_src[i0 + tid] = srd[tid];
        g_dst[i0 + tid] = srd[32 + tid];
    }
}

// ============================================================================
// Kernel 2: global max(dst) + rescaled per-node exp tables (all factors <= 1).
//   rowpack  = (E1', E2')  E1' = exp(s+Dmax-M), E2' = exp(a*(s+Dmax)-M)
//   colpack2 = (F1', F2')  F1' = exp(d-Dmax),   F2' = exp(a*(d-Dmax))
//   w_ij = max(E1'F1', E2'F2') = exp(lrelu(s_i+d_j) - M_i)
// ============================================================================
__global__ __launch_bounds__(256) void k2_params() {
    __shared__ float red[256];
    const int tid = threadIdx.x;
    float m = -1e30f;
    for (int i = tid; i < N_NODES; i += 256) m = fmaxf(m, g_dst[i]);
    red[tid] = m;
    __syncthreads();
    for (int s = 128; s > 0; s >>= 1) {
        if (tid < s) red[tid] = fmaxf(red[tid], red[tid + s]);
        __syncthreads();
    }
    const float Dmax = red[0];
    for (int i = tid; i < N_NODES; i += 256) {
        float s = g_src[i], d = g_dst[i];
        float t = s + Dmax;
        float M = (t >= 0.f) ? t : ALPHA * t;
        g_rowpack[i] = make_float4(__expf(t - M), __expf(ALPHA * t - M), 0.f, 0.f);
        g_colpack2[i] = make_float2(__expf(d - Dmax), __expf(ALPHA * (d - Dmax)));
    }
}

// ============================================================================
// Kernel 3: fused masked-softmax weights + HMMA attention GEMM.
// 512 CTAs x 256 thr, 64-row CTA, occupancy 2.
// adj+colpack 3-deep cp.async staging, B double-buffered.
// Single barrier per chunk with CORRECT protocol: consume data drained
// before the PREVIOUS barrier; this iteration's wait_group(0) comes right
// before this iteration's barrier (wait -> barrier -> consume next iter).
// ============================================================================
#define A3_OFF   0                       // 2 x 64 x 128B = 16384
#define B3_OFF   16384                   // 2 x 128 x 128B = 32768
#define ADJ3_OFF 49152                   // 3 x 64 x 256B = 49152
#define CP3_OFF  98304                   // 3 x 64 x 8B = 1536
#define RSP3_OFF 99840                   // 64 floats
#define SMEM3    100096

// stage B tile (chunk j0) into buffer bbuf — its own commit group
__device__ __forceinline__ void stage_B(uint32_t smu, int tid, int bbuf, size_t j0) {
#pragma unroll
    for (int c = 0; c < 4; ++c) {
        int idx = tid + c * 256;
        int n = idx >> 3, chn = idx & 7;
        cp16(smu + B3_OFF + bbuf * 16384 + n * 128 + ((chn ^ (n & 7)) << 4),
             &g_WhT[(size_t)n * N_NODES + j0 + chn * 8]);
    }
    CPCOMMIT();
}
// stage adj + colpack2 (chunk j0) into buffer abuf — its own commit group
__device__ __forceinline__ void stage_ADJ(uint32_t smu, int tid, int abuf,
                                          const int* adj, int i0, size_t j0) {
#pragma unroll
    for (int c = 0; c < 4; ++c) {
        int idx = tid + c * 256;
        int row = idx >> 4, seg = idx & 15;
        cp16(smu + ADJ3_OFF + abuf * 16384 + row * 256 + seg * 16,
             adj + (size_t)(i0 + row) * N_NODES + j0 + seg * 4);
    }
    if (tid < 32)
        cp16(smu + CP3_OFF + abuf * 512 + tid * 16, &g_colpack2[j0 + tid * 2]);
    CPCOMMIT();
}

__global__ __launch_bounds__(256, 2) void k3_attn(const int* __restrict__ adj) {
    extern __shared__ char sm[];
    const uint32_t smu = (uint32_t)__cvta_generic_to_shared(sm);
    const int tid = threadIdx.x, lane = tid & 31, warp = tid >> 5;
    const int split = blockIdx.x & 3;
    const int i0 = (blockIdx.x >> 2) * 64;
    const size_t jbase = (size_t)split * JCOLS;

    // wgen identity: warp rg owns rows rg*8..+7; lane cp owns cols {2cp, 2cp+1}
    const int cp = lane;
    const int rg = warp;
    const int wseg = cp >> 2, woff = (cp & 3) * 4;
    // mma identity: 2m x 4n warps, warp tile 32 rows x 32 cols
    const int wm = warp & 1, wn = warp >> 1;
    const int g = lane >> 2, t4 = lane & 3;
    const int lrA = (lane & 7) + ((lane >> 3) & 1) * 8;
    const int lkA = lane >> 4;
    const int lrB = (lane & 7) + ((lane >> 4) << 3);
    const int lkB = (lane >> 3) & 1;

    // rowpack factors for owned rows, in registers
    float rE1[8], rE2[8];
#pragma unroll
    for (int r = 0; r < 8; ++r) {
        float4 t = g_rowpack[i0 + rg * 8 + r];
        rE1[r] = t.x; rE2[r] = t.y;
    }

    float acc[2][4][4];
    float rs[8];                          // per-owned-row weight sums
#pragma unroll
    for (int mt = 0; mt < 2; ++mt)
#pragma unroll
        for (int nt = 0; nt < 4; ++nt)
#pragma unroll
            for (int e = 0; e < 4; ++e) acc[mt][nt][e] = 0.f;
#pragma unroll
    for (int r = 0; r < 8; ++r) rs[r] = 0.f;

    // wgen: adj[abuf] + colpack2[abuf] (smem) -> swizzled A tile + rsum FADDs
    auto wgen = [&](int abuf_, int cur_) {
        const float4 cc = *(const float4*)(sm + CP3_OFF + abuf_ * 512 + cp * 16);
        const char* ab = sm + ADJ3_OFF + abuf_ * 16384 + cp * 8;
        char* aw = sm + A3_OFF + cur_ * 8192;
#pragma unroll
        for (int r = 0; r < 8; ++r) {
            const int row = rg * 8 + r;
            uint2 av = *(const uint2*)(ab + row * 256);
            float w0 = fmaxf(rE1[r] * cc.x, rE2[r] * cc.y);
            float w1 = fmaxf(rE1[r] * cc.z, rE2[r] * cc.w);
            if (av.x == 0u) w0 = 0.f;
            if (av.y == 0u) w1 = 0.f;
            rs[r] += w0 + w1;
            __half2 hw = __floats2half2_rn(w0, w1);
            *(uint32_t*)(aw + row * 128 + ((wseg ^ (row & 7)) << 4) + woff) =
                *(uint32_t*)&hw;
        }
    };

    // ---- prologue ----
    // groups: ADJ0, B0, ADJ1
    stage_ADJ(smu, tid, 0, adj, i0, jbase);
    stage_B(smu, tid, 0, jbase);
    stage_ADJ(smu, tid, 1, adj, i0, jbase + 64);
    CPWAIT2();            // ADJ0 drained (mine)
    __syncthreads();      // ADJ0 visible to all
    wgen(0, 0);           // A[0]
    CPWAIT0();            // B0, ADJ1 drained
    __syncthreads();      // A[0], B0, ADJ1 visible to all

    // ---- main loop: ONE barrier per chunk (wait -> barrier -> consume) ----
    int abuf = 0;         // adj buffer of chunk t (mod 3)
    for (int t = 0; t < NC; ++t) {
        const int cur = t & 1, nxt = cur ^ 1;

        // issue stages for t+2 (adj) and t+1 (B); drained before this
        // iteration's barrier, consumed next iteration.
        if (t + 2 < NC) {
            int a2 = abuf + 2; if (a2 >= 3) a2 -= 3;
            stage_ADJ(smu, tid, a2, adj, i0, jbase + (size_t)(t + 2) * 64);
        }
        if (t + 1 < NC) stage_B(smu, tid, nxt, jbase + (size_t)(t + 1) * 64);

        // mma(t): A[cur] x B[cur] — both visible since previous barrier
        {
            const uint32_t aB = smu + A3_OFF + cur * 8192;
            const uint32_t bB = smu + B3_OFF + cur * 16384;
#pragma unroll
            for (int ks = 0; ks < 4; ++ks) {
                uint32_t a[2][4], b[2][4];
#pragma unroll
                for (int mt = 0; mt < 2; ++mt) {
                    const int row = wm * 32 + mt * 16 + lrA;
                    const int seg = 2 * ks + lkA;
                    ldsm4(a[mt][0], a[mt][1], a[mt][2], a[mt][3],
                          aB + row * 128 + ((seg ^ (row & 7)) << 4));
                }
#pragma unroll
                for (int np = 0; np < 2; ++np) {
                    const int nr = wn * 32 + np * 16 + lrB;
                    const int seg = 2 * ks + lkB;
                    ldsm4(b[np][0], b[np][1], b[np][2], b[np][3],
                          bB + nr * 128 + ((seg ^ (nr & 7)) << 4));
                }
#pragma unroll
                for (int mt = 0; mt < 2; ++mt)
#pragma unroll
                    for (int np = 0; np < 2; ++np) {
                        mma_f32(acc[mt][np * 2],     a[mt], b[np][0], b[np][1]);
                        mma_f32(acc[mt][np * 2 + 1], a[mt], b[np][2], b[np][3]);
                    }
            }
        }

        // wgen(t+1) into A[nxt] — ADJ(t+1) visible since previous barrier;
        // issues under the in-flight HMMA drain.
        if (t + 1 < NC) {
            int a1 = abuf + 1; if (a1 >= 3) a1 -= 3;
            wgen(a1, nxt);
        }

        CPWAIT0();         // drain ADJ(t+2), B(t+1) (my groups)
        __syncthreads();   // everything staged+written this iter now visible

        if (++abuf >= 3) abuf -= 3;
    }

    // ---- epilogue: partial outputs + row sums ----
    {
        float* pp = g_part + (size_t)split * N_NODES * OUT_F;
#pragma unroll
        for (int mt = 0; mt < 2; ++mt) {
            const int r0 = i0 + wm * 32 + mt * 16 + g;
#pragma unroll
            for (int nt = 0; nt < 4; ++nt) {
                const int cc = wn * 32 + nt * 8 + 2 * t4;
                *(float2*)&pp[(size_t)r0 * OUT_F + cc] =
                    make_float2(acc[mt][nt][0], acc[mt][nt][1]);
                *(float2*)&pp[(size_t)(r0 + 8) * OUT_F + cc] =
                    make_float2(acc[mt][nt][2], acc[mt][nt][3]);
            }
        }
    }
    // row sums: warp-reduce rs[r] across 32 col-owner lanes
    float* rsp = (float*)(sm + RSP3_OFF);
#pragma unroll
    for (int r = 0; r < 8; ++r) {
        float v = rs[r];
#pragma unroll
        for (int off = 16; off > 0; off >>= 1)
            v += __shfl_xor_sync(0xffffffffu, v, off);
        if (lane == 0) rsp[rg * 8 + r] = v;
    }
    __syncthreads();
    if (tid < 64) g_rsum[split * N_NODES + i0 + tid] = rsp[tid];
}

// ============================================================================
// Kernel 4: combine 4 split partials, normalize, ELU, store. 1 float4/thread.
// ============================================================================
__device__ __forceinline__ float elu1(float x) {
    return x > 0.f ? x : (__expf(x) - 1.f);
}

__global__ __launch_bounds__(256) void k4_fin(float* __restrict__ out) {
    int gi = blockIdx.x * 256 + threadIdx.x;      // 262144 threads
    int row = gi >> 5;
    int cof = (gi & 31) * 4;
    const float* pb = g_part + (size_t)row * OUT_F + cof;
    float4 a = *(const float4*)pb;
    float4 b = *(const float4*)(pb + (size_t)N_NODES * OUT_F);
    float4 c = *(const float4*)(pb + 2 * (size_t)N_NODES * OUT_F);
    float4 d = *(const float4*)(pb + 3 * (size_t)N_NODES * OUT_F);
    float s = g_rsum[row] + g_rsum[N_NODES + row]
            + g_rsum[2 * N_NODES + row] + g_rsum[3 * N_NODES + row];
    float rinv = 1.f / s;
    float4 o;
    o.x = elu1((a.x + b.x + c.x + d.x) * rinv);
    o.y = elu1((a.y + b.y + c.y + d.y) * rinv);
    o.z = elu1((a.z + b.z + c.z + d.z) * rinv);
    o.w = elu1((a.w + b.w + c.w + d.w) * rinv);
    *(float4*)(out + (size_t)row * OUT_F + cof) = o;
}

// ============================================================================
extern "C" void kernel_launch(void* const* d_in, const int* in_sizes, int n_in,
                              void* d_out, int out_size) {
    const float* h   = (const float*)d_in[0];
    const int*   adj = (const int*)d_in[1];
    const float* W   = (const float*)d_in[2];
    const float* a   = (const float*)d_in[3];
    float* out = (float*)d_out;
    (void)in_sizes; (void)n_in; (void)out_size;

    cudaFuncSetAttribute(k1_wh, cudaFuncAttributeMaxDynamicSharedMemorySize, SMEM1);
    cudaFuncSetAttribute(k3_attn, cudaFuncAttributeMaxDynamicSharedMemorySize, SMEM3);

    k0_wt<<<(IN_F * OUT_F) / 256, 256>>>(W);
    k1_wh<<<N_NODES / 32, 256, SMEM1>>>(h, a);
    k2_params<<<1, 256>>>();
    k3_attn<<<(N_NODES / 64) * NSPLIT, 256, SMEM3>>>(adj);
    k4_fin<<<(N_NODES * OUT_F / 4) / 256, 256>>>(out);
}